// round 5
// baseline (speedup 1.0000x reference)
#include <cuda_runtime.h>
#include <math.h>

// Problem constants (fixed by reference setup_inputs)
#define BB    512
#define KK    8
#define PP    6
#define DD    1024
#define NIDS  64
#define NGRP  (2 * NIDS)          // (mod, id) groups
#define MARGIN 0.2f

// Scratch (no allocations allowed)
__device__ float g_w[BB];         // fused per-sample weight (includes 1/(grp*K*P*denom))
__device__ float g_cinv[BB];      // 1/max(cnt_cross,1)
__device__ int   g_boff[BB];      // CSR offset of sample b's CROSS group
__device__ int   g_bcnt[BB];      // count of sample b's CROSS group
__device__ int   g_list[BB];      // CSR sample indices grouped by (mod,id)

// ---------------------------------------------------------------------------
// K1: one block, 512 threads. Counts, validity, id_count, fused weights,
//     per-sample cross-group CSR (offset,count), zero d_out.
// ---------------------------------------------------------------------------
__global__ void k1_setup(const int* __restrict__ pids,
                         const int* __restrict__ camids,
                         float* __restrict__ out) {
    __shared__ int scnt[NGRP];        // [mod][id], mod 0 = rgb, 1 = sar
    __shared__ int scur[NGRP];
    __shared__ int soff[NGRP + 1];
    __shared__ int svalid[NIDS];
    __shared__ int s_idcount;

    int t = threadIdx.x;
    if (t < NGRP) { scnt[t] = 0; scur[t] = 0; }
    if (t == 0) s_idcount = 0;
    __syncthreads();

    int pid = 0, cam = 0, own_grp = 0;
    if (t < BB) {
        pid = pids[t];
        cam = camids[t];
        int mod = (cam == 0) ? 0 : 1;              // own modality
        own_grp = mod * NIDS + pid;
        atomicAdd(&scnt[own_grp], 1);
    }
    __syncthreads();

    if (t < NIDS) {
        int v = (scnt[t] > 0 && scnt[NIDS + t] > 0) ? 1 : 0;
        svalid[t] = v;
        if (v) atomicAdd(&s_idcount, 1);
    }
    __syncthreads();

    if (t == 0) {                                  // serial prefix over 128 groups
        int acc = 0;
        for (int g = 0; g < NGRP; ++g) { soff[g] = acc; acc += scnt[g]; }
        soff[NGRP] = acc;
    }
    __syncthreads();

    float denom = fmaxf((float)s_idcount, 1.0f);

    if (t < BB) {
        int rgb = (cam == 0);
        int cross_grp = (rgb ? 1 : 0) * NIDS + pid;
        float grp_cnt = fmaxf((float)scnt[own_grp], 1.0f);
        float w = svalid[pid] ? (1.0f / (grp_cnt * (float)KK * (float)PP * denom)) : 0.0f;
        g_w[t] = w;
        g_cinv[t] = 1.0f / fmaxf((float)scnt[cross_grp], 1.0f);
        g_boff[t] = soff[cross_grp];
        g_bcnt[t] = scnt[cross_grp];
        int pos = atomicAdd(&scur[own_grp], 1);
        g_list[soff[own_grp] + pos] = t;
    }
    if (t == 0) out[0] = 0.0f;
}

// ---------------------------------------------------------------------------
// K4: one block per (b,p).
//   1. Batch-issue 8 streaming f_gen float4 loads (overlap with prologue).
//   2. Stage own f_original row + gathered cross-center row in SMEM
//      (member list broadcast via shfl; member rows loaded 4-at-a-time).
//   3. Warp k computes pull/push distances for f_generated[b,k,p,:].
// ---------------------------------------------------------------------------
__global__ void __launch_bounds__(256) k4_main(const float* __restrict__ f_orig,
                                               const float* __restrict__ f_gen,
                                               float* __restrict__ out) {
    __shared__ float so[DD];          // own f_original row
    __shared__ float sc[DD];          // cross-modality center row
    __shared__ float spart[8];

    int bp = blockIdx.x;              // 0 .. B*P-1
    int b = bp / PP;
    int p = bp - b * PP;
    int t = threadIdx.x;              // 256 threads; thread t owns float4 #t
    int k = t >> 5;
    int lane = t & 31;

    // --- 1. f_gen stream first (no SMEM dependence) ---
    const float4* gp = reinterpret_cast<const float4*>(
        f_gen + ((size_t)((b * KK + k) * PP + p)) * DD);
    float4 g[8];
#pragma unroll
    for (int it = 0; it < 8; ++it) g[it] = __ldcs(&gp[it * 32 + lane]);

    // --- 2. prologue: own row + center gather ---
    const float4* fo4 = reinterpret_cast<const float4*>(f_orig);
    float4 o4 = fo4[(((size_t)(b * PP + p) * DD) >> 2) + t];
    reinterpret_cast<float4*>(so)[t] = o4;

    int off = g_boff[b];
    int cnt = g_bcnt[b];
    float cinv = g_cinv[b];

    float4 acc = make_float4(0.f, 0.f, 0.f, 0.f);
    for (int base = 0; base < cnt; base += 32) {
        int n = cnt - base; if (n > 32) n = 32;
        int idx = (lane < n) ? g_list[off + base + lane] : 0;
        int j = 0;
        for (; j + 4 <= n; j += 4) {
            int b0 = __shfl_sync(0xffffffffu, idx, j + 0);
            int b1 = __shfl_sync(0xffffffffu, idx, j + 1);
            int b2 = __shfl_sync(0xffffffffu, idx, j + 2);
            int b3 = __shfl_sync(0xffffffffu, idx, j + 3);
            float4 v0 = fo4[(((size_t)(b0 * PP + p) * DD) >> 2) + t];
            float4 v1 = fo4[(((size_t)(b1 * PP + p) * DD) >> 2) + t];
            float4 v2 = fo4[(((size_t)(b2 * PP + p) * DD) >> 2) + t];
            float4 v3 = fo4[(((size_t)(b3 * PP + p) * DD) >> 2) + t];
            acc.x += (v0.x + v1.x) + (v2.x + v3.x);
            acc.y += (v0.y + v1.y) + (v2.y + v3.y);
            acc.z += (v0.z + v1.z) + (v2.z + v3.z);
            acc.w += (v0.w + v1.w) + (v2.w + v3.w);
        }
        for (; j < n; ++j) {
            int bs = __shfl_sync(0xffffffffu, idx, j);
            float4 v = fo4[(((size_t)(bs * PP + p) * DD) >> 2) + t];
            acc.x += v.x; acc.y += v.y; acc.z += v.z; acc.w += v.w;
        }
    }
    acc.x *= cinv; acc.y *= cinv; acc.z *= cinv; acc.w *= cinv;
    reinterpret_cast<float4*>(sc)[t] = acc;
    __syncthreads();

    // --- 3. main compute: g regs vs SMEM rows ---
    float s_pull = 0.0f, s_push = 0.0f;
#pragma unroll
    for (int it = 0; it < 8; ++it) {
        float4 o = reinterpret_cast<const float4*>(so)[it * 32 + lane];
        float4 c = reinterpret_cast<const float4*>(sc)[it * 32 + lane];
        float dx, dy, dz, dw;
        dx = g[it].x - c.x; dy = g[it].y - c.y;
        dz = g[it].z - c.z; dw = g[it].w - c.w;
        s_pull += dx * dx + dy * dy + dz * dz + dw * dw;
        dx = g[it].x - o.x; dy = g[it].y - o.y;
        dz = g[it].z - o.z; dw = g[it].w - o.w;
        s_push += dx * dx + dy * dy + dz * dz + dw * dw;
    }
#pragma unroll
    for (int off2 = 16; off2; off2 >>= 1) {
        s_pull += __shfl_down_sync(0xffffffffu, s_pull, off2);
        s_push += __shfl_down_sync(0xffffffffu, s_push, off2);
    }
    if (lane == 0) {
        float h = sqrtf(s_pull) - sqrtf(s_push) + MARGIN;
        spart[k] = fmaxf(h, 0.0f) * g_w[b];
    }
    __syncthreads();
    if (t == 0) {
        float s = 0.0f;
#pragma unroll
        for (int i = 0; i < 8; ++i) s += spart[i];
        atomicAdd(out, s);
    }
}

// ---------------------------------------------------------------------------
extern "C" void kernel_launch(void* const* d_in, const int* in_sizes, int n_in,
                              void* d_out, int out_size) {
    const float* f_orig = (const float*)d_in[0];
    const float* f_gen  = (const float*)d_in[1];
    const int*   pids   = (const int*)d_in[2];
    const int*   camids = (const int*)d_in[3];
    float*       out    = (float*)d_out;

    k1_setup<<<1, 512>>>(pids, camids, out);
    k4_main<<<BB * PP, 256>>>(f_orig, f_gen, out);
}

// round 6
// speedup vs baseline: 1.0682x; 1.0682x over previous
#include <cuda_runtime.h>
#include <math.h>

// Problem constants (fixed by reference setup_inputs)
#define BB    512
#define KK    8
#define PP    6
#define DD    1024
#define NIDS  64
#define NGRP  (2 * NIDS)          // (mod, id) groups
#define MARGIN 0.2f
#define ROW4  (DD / 4)            // 256 float4 per D-row
#define BP4   (PP * ROW4)         // 1536 float4 per [P,D] slab

// Scratch (no allocations allowed)
__device__ float g_w[BB];         // fused per-sample weight (1/(grp*K*P*denom))
__device__ float g_cinv[BB];      // 1/max(cnt_cross,1)
__device__ int   g_boff[BB];      // CSR offset of sample b's CROSS group
__device__ int   g_bcnt[BB];      // count of sample b's CROSS group
__device__ int   g_list[BB];      // CSR sample indices grouped by (mod,id)

// ---------------------------------------------------------------------------
// K1: one block, 512 threads. Counts, validity, id_count, fused weights,
//     per-sample cross-group CSR (offset,count), zero d_out.
// ---------------------------------------------------------------------------
__global__ void k1_setup(const int* __restrict__ pids,
                         const int* __restrict__ camids,
                         float* __restrict__ out) {
    __shared__ int scnt[NGRP];
    __shared__ int scur[NGRP];
    __shared__ int soff[NGRP + 1];
    __shared__ int svalid[NIDS];
    __shared__ int s_idcount;

    int t = threadIdx.x;
    if (t < NGRP) { scnt[t] = 0; scur[t] = 0; }
    if (t == 0) s_idcount = 0;
    __syncthreads();

    int pid = 0, cam = 0, own_grp = 0;
    if (t < BB) {
        pid = pids[t];
        cam = camids[t];
        int mod = (cam == 0) ? 0 : 1;
        own_grp = mod * NIDS + pid;
        atomicAdd(&scnt[own_grp], 1);
    }
    __syncthreads();

    if (t < NIDS) {
        int v = (scnt[t] > 0 && scnt[NIDS + t] > 0) ? 1 : 0;
        svalid[t] = v;
        if (v) atomicAdd(&s_idcount, 1);
    }
    __syncthreads();

    if (t == 0) {
        int acc = 0;
        for (int g = 0; g < NGRP; ++g) { soff[g] = acc; acc += scnt[g]; }
        soff[NGRP] = acc;
    }
    __syncthreads();

    float denom = fmaxf((float)s_idcount, 1.0f);

    if (t < BB) {
        int rgb = (cam == 0);
        int cross_grp = (rgb ? 1 : 0) * NIDS + pid;
        float grp_cnt = fmaxf((float)scnt[own_grp], 1.0f);
        float w = svalid[pid] ? (1.0f / (grp_cnt * (float)KK * (float)PP * denom)) : 0.0f;
        g_w[t] = w;
        g_cinv[t] = 1.0f / fmaxf((float)scnt[cross_grp], 1.0f);
        g_boff[t] = soff[cross_grp];
        g_bcnt[t] = scnt[cross_grp];
        int pos = atomicAdd(&scur[own_grp], 1);
        g_list[soff[own_grp] + pos] = t;
    }
    if (t == 0) out[0] = 0.0f;
}

// ---------------------------------------------------------------------------
// K4: one block per b. Stage full own [P,D] slab + cross-center [P,D] slab
//     in SMEM, then 8 warps each stream 6 rows of f_gen[b] (K*P = 48 rows).
// ---------------------------------------------------------------------------
__global__ void __launch_bounds__(256) k4_main(const float* __restrict__ f_orig,
                                               const float* __restrict__ f_gen,
                                               float* __restrict__ out) {
    __shared__ float so[PP * DD];     // own f_original slab   (24 KB)
    __shared__ float sc[PP * DD];     // cross center slab     (24 KB)

    int b = blockIdx.x;
    int t = threadIdx.x;              // 256 threads
    int w = t >> 5;
    int lane = t & 31;

    const float4* fo4 = reinterpret_cast<const float4*>(f_orig);
    float4* so4 = reinterpret_cast<float4*>(so);
    float4* sc4 = reinterpret_cast<float4*>(sc);

    // --- Prologue: stage own slab + gather cross-center slab ---
    const float4* own = fo4 + (size_t)b * BP4;
#pragma unroll
    for (int i = 0; i < 6; ++i) so4[i * 256 + t] = own[i * 256 + t];

    int off = g_boff[b];
    int cnt = g_bcnt[b];
    float cinv = g_cinv[b];

    float4 acc[6];
#pragma unroll
    for (int i = 0; i < 6; ++i) acc[i] = make_float4(0.f, 0.f, 0.f, 0.f);
    for (int j = 0; j < cnt; ++j) {
        int bs = g_list[off + j];
        const float4* mp = fo4 + (size_t)bs * BP4;
#pragma unroll
        for (int i = 0; i < 6; ++i) {
            float4 v = mp[i * 256 + t];
            acc[i].x += v.x; acc[i].y += v.y; acc[i].z += v.z; acc[i].w += v.w;
        }
    }
#pragma unroll
    for (int i = 0; i < 6; ++i) {
        acc[i].x *= cinv; acc[i].y *= cinv; acc[i].z *= cinv; acc[i].w *= cinv;
        sc4[i * 256 + t] = acc[i];
    }
    __syncthreads();

    // --- Main stream: warp w handles rows r = w*6 .. w*6+5 of f_gen[b] ---
    const float4* gbase = reinterpret_cast<const float4*>(f_gen) +
                          (size_t)b * (KK * PP * ROW4);
    float hsum = 0.0f;
#pragma unroll
    for (int j = 0; j < 6; ++j) {
        int r = w * 6 + j;            // 0..47, r = k*PP + p
        int p = r % PP;
        const float4* gp = gbase + r * ROW4;

        float4 g[8];
#pragma unroll
        for (int it = 0; it < 8; ++it) g[it] = __ldcs(&gp[it * 32 + lane]);

        float s_pull = 0.0f, s_push = 0.0f;
#pragma unroll
        for (int it = 0; it < 8; ++it) {
            float4 o = so4[p * 256 + it * 32 + lane];
            float4 c = sc4[p * 256 + it * 32 + lane];
            float dx, dy, dz, dw;
            dx = g[it].x - c.x; dy = g[it].y - c.y;
            dz = g[it].z - c.z; dw = g[it].w - c.w;
            s_pull += dx * dx + dy * dy + dz * dz + dw * dw;
            dx = g[it].x - o.x; dy = g[it].y - o.y;
            dz = g[it].z - o.z; dw = g[it].w - o.w;
            s_push += dx * dx + dy * dy + dz * dz + dw * dw;
        }
#pragma unroll
        for (int s = 16; s; s >>= 1) {
            s_pull += __shfl_down_sync(0xffffffffu, s_pull, s);
            s_push += __shfl_down_sync(0xffffffffu, s_push, s);
        }
        if (lane == 0) {
            float h = sqrtf(s_pull) - sqrtf(s_push) + MARGIN;
            hsum += fmaxf(h, 0.0f);
        }
    }

    // --- Epilogue: block reduce (reuse so), one atomic per block ---
    __syncthreads();
    if (lane == 0) so[w] = hsum;
    __syncthreads();
    if (t == 0) {
        float s = 0.0f;
#pragma unroll
        for (int i = 0; i < 8; ++i) s += so[i];
        atomicAdd(out, s * g_w[b]);
    }
}

// ---------------------------------------------------------------------------
extern "C" void kernel_launch(void* const* d_in, const int* in_sizes, int n_in,
                              void* d_out, int out_size) {
    const float* f_orig = (const float*)d_in[0];
    const float* f_gen  = (const float*)d_in[1];
    const int*   pids   = (const int*)d_in[2];
    const int*   camids = (const int*)d_in[3];
    float*       out    = (float*)d_out;

    k1_setup<<<1, 512>>>(pids, camids, out);
    k4_main<<<BB, 256>>>(f_orig, f_gen, out);
}

// round 7
// speedup vs baseline: 1.1325x; 1.0602x over previous
#include <cuda_runtime.h>
#include <math.h>

// Problem constants (fixed by reference setup_inputs)
#define BB    512
#define KK    8
#define PP    6
#define NPAIR 3                   // PP/2 row-pairs
#define DD    1024
#define NIDS  64
#define NGRP  (2 * NIDS)          // (mod, id) groups
#define MARGIN 0.2f
#define ROW4  (DD / 4)            // 256 float4 per D-row

// Scratch (no allocations allowed)
__device__ float g_w[BB];         // fused per-sample weight (1/(grp*K*P*denom))
__device__ float g_cinv[BB];      // 1/max(cnt_cross,1)
__device__ int   g_boff[BB];      // CSR offset of sample b's CROSS group
__device__ int   g_bcnt[BB];      // count of sample b's CROSS group
__device__ int   g_list[BB];      // CSR sample indices grouped by (mod,id)

// ---------------------------------------------------------------------------
// K1: one block, 512 threads. Counts, validity, id_count, fused weights,
//     per-sample cross-group CSR (offset,count), zero d_out.
// ---------------------------------------------------------------------------
__global__ void k1_setup(const int* __restrict__ pids,
                         const int* __restrict__ camids,
                         float* __restrict__ out) {
    __shared__ int scnt[NGRP];
    __shared__ int scur[NGRP];
    __shared__ int soff[NGRP + 1];
    __shared__ int svalid[NIDS];
    __shared__ int s_idcount;

    int t = threadIdx.x;
    if (t < NGRP) { scnt[t] = 0; scur[t] = 0; }
    if (t == 0) s_idcount = 0;
    __syncthreads();

    int pid = 0, cam = 0, own_grp = 0;
    if (t < BB) {
        pid = pids[t];
        cam = camids[t];
        int mod = (cam == 0) ? 0 : 1;
        own_grp = mod * NIDS + pid;
        atomicAdd(&scnt[own_grp], 1);
    }
    __syncthreads();

    if (t < NIDS) {
        int v = (scnt[t] > 0 && scnt[NIDS + t] > 0) ? 1 : 0;
        svalid[t] = v;
        if (v) atomicAdd(&s_idcount, 1);
    }
    __syncthreads();

    if (t == 0) {
        int acc = 0;
        for (int g = 0; g < NGRP; ++g) { soff[g] = acc; acc += scnt[g]; }
        soff[NGRP] = acc;
    }
    __syncthreads();

    float denom = fmaxf((float)s_idcount, 1.0f);

    if (t < BB) {
        int rgb = (cam == 0);
        int cross_grp = (rgb ? 1 : 0) * NIDS + pid;
        float grp_cnt = fmaxf((float)scnt[own_grp], 1.0f);
        float w = svalid[pid] ? (1.0f / (grp_cnt * (float)KK * (float)PP * denom)) : 0.0f;
        g_w[t] = w;
        g_cinv[t] = 1.0f / fmaxf((float)scnt[cross_grp], 1.0f);
        g_boff[t] = soff[cross_grp];
        g_bcnt[t] = scnt[cross_grp];
        int pos = atomicAdd(&scur[own_grp], 1);
        g_list[soff[own_grp] + pos] = t;
    }
    if (t == 0) out[0] = 0.0f;
}

// ---------------------------------------------------------------------------
// K4: one block per (b, p-pair). Stage 2 rows of own f_original + 2 rows of
//     cross-center in SMEM, then warp k streams its 2 contiguous f_gen rows.
//     1536 blocks, 256 threads, ~16 KB SMEM, regs capped for 5 blocks/SM.
// ---------------------------------------------------------------------------
__global__ void __launch_bounds__(256, 5) k4_main(const float* __restrict__ f_orig,
                                                  const float* __restrict__ f_gen,
                                                  float* __restrict__ out) {
    __shared__ float so[2 * DD];      // own rows (p, p+1)       8 KB
    __shared__ float sc[2 * DD];      // cross-center rows        8 KB
    __shared__ float spart[8];

    int bp = blockIdx.x;              // 0 .. BB*NPAIR-1
    int b = bp / NPAIR;
    int pp = (bp - b * NPAIR) * 2;    // first p of the pair
    int t = threadIdx.x;              // 256 threads
    int w = t >> 5;                   // warp = k index
    int lane = t & 31;

    const float4* fo4 = reinterpret_cast<const float4*>(f_orig);
    float4* so4 = reinterpret_cast<float4*>(so);
    float4* sc4 = reinterpret_cast<float4*>(sc);

    // --- Prologue: stage own row-pair (contiguous 512 float4) ---
    size_t obase = ((size_t)(b * PP + pp) * DD) >> 2;
    so4[t]       = fo4[obase + t];
    so4[256 + t] = fo4[obase + 256 + t];

    // --- Gather cross-center row-pair: 2 independent loads per member ---
    int off = g_boff[b];
    int cnt = g_bcnt[b];
    float cinv = g_cinv[b];
    float4 a0 = make_float4(0.f, 0.f, 0.f, 0.f);
    float4 a1 = make_float4(0.f, 0.f, 0.f, 0.f);
    for (int j = 0; j < cnt; ++j) {
        int bs = g_list[off + j];
        size_t mb = ((size_t)(bs * PP + pp) * DD) >> 2;
        float4 v0 = fo4[mb + t];
        float4 v1 = fo4[mb + 256 + t];
        a0.x += v0.x; a0.y += v0.y; a0.z += v0.z; a0.w += v0.w;
        a1.x += v1.x; a1.y += v1.y; a1.z += v1.z; a1.w += v1.w;
    }
    a0.x *= cinv; a0.y *= cinv; a0.z *= cinv; a0.w *= cinv;
    a1.x *= cinv; a1.y *= cinv; a1.z *= cinv; a1.w *= cinv;
    sc4[t] = a0;
    sc4[256 + t] = a1;
    __syncthreads();

    // --- Main: warp w streams f_gen rows (b, w, pp) and (b, w, pp+1) ---
    const float4* gbase = reinterpret_cast<const float4*>(f_gen) +
                          (((size_t)(b * KK + w) * PP + pp) * DD >> 2);
    float hsum = 0.0f;
#pragma unroll
    for (int jr = 0; jr < 2; ++jr) {
        const float4* gp = gbase + jr * ROW4;
        float4 g[8];
#pragma unroll
        for (int it = 0; it < 8; ++it) g[it] = __ldcs(&gp[it * 32 + lane]);

        float s_pull = 0.0f, s_push = 0.0f;
#pragma unroll
        for (int it = 0; it < 8; ++it) {
            float4 o = so4[jr * 256 + it * 32 + lane];
            float4 c = sc4[jr * 256 + it * 32 + lane];
            float dx, dy, dz, dw;
            dx = g[it].x - c.x; dy = g[it].y - c.y;
            dz = g[it].z - c.z; dw = g[it].w - c.w;
            s_pull += dx * dx + dy * dy + dz * dz + dw * dw;
            dx = g[it].x - o.x; dy = g[it].y - o.y;
            dz = g[it].z - o.z; dw = g[it].w - o.w;
            s_push += dx * dx + dy * dy + dz * dz + dw * dw;
        }
#pragma unroll
        for (int s = 16; s; s >>= 1) {
            s_pull += __shfl_down_sync(0xffffffffu, s_pull, s);
            s_push += __shfl_down_sync(0xffffffffu, s_push, s);
        }
        if (lane == 0) {
            float h = sqrtf(s_pull) - sqrtf(s_push) + MARGIN;
            hsum += fmaxf(h, 0.0f);
        }
    }

    // --- Epilogue: block reduce, one atomic ---
    if (lane == 0) spart[w] = hsum;
    __syncthreads();
    if (t == 0) {
        float s = 0.0f;
#pragma unroll
        for (int i = 0; i < 8; ++i) s += spart[i];
        atomicAdd(out, s * g_w[b]);
    }
}

// ---------------------------------------------------------------------------
extern "C" void kernel_launch(void* const* d_in, const int* in_sizes, int n_in,
                              void* d_out, int out_size) {
    const float* f_orig = (const float*)d_in[0];
    const float* f_gen  = (const float*)d_in[1];
    const int*   pids   = (const int*)d_in[2];
    const int*   camids = (const int*)d_in[3];
    float*       out    = (float*)d_out;

    k1_setup<<<1, 512>>>(pids, camids, out);
    k4_main<<<BB * NPAIR, 256>>>(f_orig, f_gen, out);
}